// round 10
// baseline (speedup 1.0000x reference)
#include <cuda_runtime.h>
#include <cstdint>

typedef unsigned long long u64;
#define DEV static __device__ __forceinline__

static constexpr int L_ = 3;
static constexpr int NB = 256;   // 256 CTAs, 4 rows each, 2 CTAs/SM
static constexpr int NT = 256;   // 8 warps

// ---------------- device globals ----------------
__device__ float g_P[2][1024 * 128];   // double-buffered Pj
__device__ float g_Wc[L_][128 * 128];  // ew2 @ nw1b
__device__ float g_cb[L_][128];        // eb2 @ nw1b
__device__ unsigned g_bar[4];          // monotonic barrier counters (replay-safe)

// ---------------- f32x2 helpers ----------------
DEV u64 pk(float lo, float hi) {
    u64 r; asm("mov.b64 %0,{%1,%2};" : "=l"(r) : "f"(lo), "f"(hi)); return r;
}
DEV void upk(u64 v, float& lo, float& hi) {
    asm("mov.b64 {%0,%1},%2;" : "=f"(lo), "=f"(hi) : "l"(v));
}
DEV u64 add2(u64 a, u64 b) {
    u64 r; asm("add.rn.f32x2 %0,%1,%2;" : "=l"(r) : "l"(a), "l"(b)); return r;
}
DEV u64 fma2(u64 a, u64 b, u64 c) {
    u64 r; asm("fma.rn.f32x2 %0,%1,%2,%3;" : "=l"(r) : "l"(a), "l"(b), "l"(c)); return r;
}
DEV u64 relu2(u64 v) {
    float lo, hi; upk(v, lo, hi);
    return pk(fmaxf(lo, 0.f), fmaxf(hi, 0.f));
}

// ---------------- cp.async helpers ----------------
DEV void cpa16(void* dst, const void* src) {
    unsigned d = (unsigned)__cvta_generic_to_shared(dst);
    asm volatile("cp.async.cg.shared.global [%0],[%1],16;" :: "r"(d), "l"(src) : "memory");
}
DEV void cpa_commit() { asm volatile("cp.async.commit_group;" ::: "memory"); }
DEV void cpa_wait0() { asm volatile("cp.async.wait_group 0;" ::: "memory"); }
DEV void cpa_wait1() { asm volatile("cp.async.wait_group 1;" ::: "memory"); }

// stage 32KB (8192 floats) with 256 threads, one commit group
DEV void stage32(float* dst, const float* src, int tid) {
#pragma unroll
    for (int i = 0; i < 8; i++)
        cpa16(dst + (i * 256 + tid) * 4, src + (i * 256 + tid) * 4);
    cpa_commit();
}

// ---------------- split grid barrier (monotonic counters; replay-safe) ----------------
DEV unsigned ld_acq(const unsigned* p) {
    unsigned v;
    asm volatile("ld.acquire.gpu.global.u32 %0,[%1];" : "=r"(v) : "l"(p) : "memory");
    return v;
}
DEV void bar_arrive(int bidx, int tid, unsigned* sT) {
    __syncthreads();
    if (tid == 0) {
        __threadfence();
        unsigned t = atomicAdd(&g_bar[bidx], 1u);
        *sT = (t / (unsigned)NB + 1u) * (unsigned)NB;
    }
}
DEV void bar_wait(int bidx, int tid, unsigned* sT) {
    __syncthreads();
    if (tid == 0) {
        unsigned target = *sT;
        while (ld_acq(&g_bar[bidx]) < target) { __nanosleep(64); }
        __threadfence();
    }
    __syncthreads();
}

// ---------------- GEMM half: 4 rows x 128 cols over 64 k (one 32KB buffer) ----------
// warp kq in [0,8) handles 8 k's; lane = 4 cols.
// dup'd A: ATs[k*10 + 2r] = ATs[k*10+2r+1] = A[r][k]   (r < 4)
DEV void gemm_half(const float* __restrict__ ATs, const float* __restrict__ buf,
                   int lane, int kq, int h, u64 acc[4][2]) {
    const float* ap = ATs + (h * 64 + kq * 8) * 10;
    const float* wp = buf + kq * 8 * 128 + lane * 4;
#pragma unroll
    for (int k = 0; k < 8; k++) {
        ulonglong2 a01 = *(const ulonglong2*)(ap + k * 10);      // (r0 dup, r1 dup)
        ulonglong2 a23 = *(const ulonglong2*)(ap + k * 10 + 4);  // (r2 dup, r3 dup)
        ulonglong2 wv = *(const ulonglong2*)(wp + k * 128);      // ((c0,c1),(c2,c3))
        acc[0][0] = fma2(a01.x, wv.x, acc[0][0]);
        acc[0][1] = fma2(a01.x, wv.y, acc[0][1]);
        acc[1][0] = fma2(a01.y, wv.x, acc[1][0]);
        acc[1][1] = fma2(a01.y, wv.y, acc[1][1]);
        acc[2][0] = fma2(a23.x, wv.x, acc[2][0]);
        acc[2][1] = fma2(a23.x, wv.y, acc[2][1]);
        acc[3][0] = fma2(a23.y, wv.x, acc[3][0]);
        acc[3][1] = fma2(a23.y, wv.y, acc[3][1]);
    }
}

DEV void store_part4(float* sPart, const u64 acc[4][2], int lane, int kq) {
    float* o = sPart + kq * 512 + lane * 4;
#pragma unroll
    for (int r = 0; r < 4; r++) {
        float v0, v1, v2, v3;
        upk(acc[r][0], v0, v1); upk(acc[r][1], v2, v3);
        *(float4*)(o + r * 128) = make_float4(v0, v1, v2, v3);
    }
}

DEV float reduce8(const float* __restrict__ sPart, int idx) {
    float v = 0.f;
#pragma unroll
    for (int p = 0; p < 8; p++) v += sPart[p * 512 + idx];
    return v;
}

// ---------------- agg quarter: buf = 64 j x 128 d; warp jq handles 8 j's ----------
DEV void agg_q(const float* __restrict__ buf, const float* __restrict__ adq,
               const u64 xi[4][2], u64 acc[4][2], int lane, int jq) {
    const float* pj = buf + jq * 8 * 128 + lane * 4;
    const float* ad = adq + jq * 8 * 8;
#pragma unroll
    for (int jj = 0; jj < 8; jj++) {
        ulonglong2 xj = *(const ulonglong2*)(pj + jj * 128);
        ulonglong2 a01 = *(const ulonglong2*)(ad + jj * 8);      // (dup a_i0, dup a_i1)
        ulonglong2 a23 = *(const ulonglong2*)(ad + jj * 8 + 4);  // (dup a_i2, dup a_i3)
        u64 t;
        t = relu2(add2(xi[0][0], xj.x)); acc[0][0] = fma2(t, a01.x, acc[0][0]);
        t = relu2(add2(xi[0][1], xj.y)); acc[0][1] = fma2(t, a01.x, acc[0][1]);
        t = relu2(add2(xi[1][0], xj.x)); acc[1][0] = fma2(t, a01.y, acc[1][0]);
        t = relu2(add2(xi[1][1], xj.y)); acc[1][1] = fma2(t, a01.y, acc[1][1]);
        t = relu2(add2(xi[2][0], xj.x)); acc[2][0] = fma2(t, a23.x, acc[2][0]);
        t = relu2(add2(xi[2][1], xj.y)); acc[2][1] = fma2(t, a23.x, acc[2][1]);
        t = relu2(add2(xi[3][0], xj.x)); acc[3][0] = fma2(t, a23.y, acc[3][0]);
        t = relu2(add2(xi[3][1], xj.y)); acc[3][1] = fma2(t, a23.y, acc[3][1]);
    }
}

// ---------------- smem layout (floats) ----------------
// b0 0 (8192) | b1 8192 (8192) | sPart 16384 (4096) | sATs 20480 (1280)
// sNTs 21760 (1280) | sPi 23040 (512) | sPn 23552 (512) | sAdj2 24064 (2048)
// s_rs 26112 (4) | sX 26116 (512) | sBarT 26628 (1)
static constexpr int SMEM_FLOATS = 26629;   // 106516 B  -> 2 CTAs/SM

__global__ void __launch_bounds__(NT, 2) k_main(
    float* __restrict__ x, const float* __restrict__ nf, const float* __restrict__ adj,
    const float* __restrict__ ew1, const float* __restrict__ eb1,
    const float* __restrict__ ew2, const float* __restrict__ eb2,
    const float* __restrict__ nw1, const float* __restrict__ nb1,
    const float* __restrict__ nw2, const float* __restrict__ nb2) {
    extern __shared__ float sm[];
    float* b0 = sm;
    float* b1 = sm + 8192;
    float* sPart = sm + 16384;
    float* sATs = sm + 20480;
    float* sNTs = sm + 21760;
    float* sPi = sm + 23040;
    float* sPn = sm + 23552;
    float* sAdj2 = sm + 24064;
    float* s_rs = sm + 26112;
    float* sX = sm + 26116;
    unsigned* sBarT = (unsigned*)(sm + 26628);

    int tid = threadIdx.x, lane = tid & 31, w = tid >> 5;   // w = kq = jq
    int rb = blockIdx.x;        // rows rb*4 .. rb*4+3
    int b = rb >> 6;            // batch (64 CTAs per batch)
    int il0 = (rb & 63) * 4;    // local i base in batch

    // ================= setup: Wc/cb producers, arrive, local setup, wait =========
    if (rb < 96) {   // Wc[l] rows r4*4..+3 = ew2[l] @ nw1b[l]
        int l = rb / 32, r4 = rb % 32;
        stage32(b0, nw1 + l * 32768 + 16384, tid);
        stage32(b1, nw1 + l * 32768 + 16384 + 8192, tid);
#pragma unroll
        for (int q = 0; q < 2; q++) {
            int idx = q * 256 + tid;
            int r = idx >> 7, k = idx & 127;
            float v = ew2[l * 16384 + (r4 * 4 + r) * 128 + k];
            *(float2*)(sATs + k * 10 + 2 * r) = make_float2(v, v);
        }
        cpa_wait0();
        __syncthreads();
        u64 acc[4][2] = {};
        gemm_half(sATs, b0, lane, w, 0, acc);
        gemm_half(sATs, b1, lane, w, 1, acc);
        store_part4(sPart, acc, lane, w);
        __syncthreads();
#pragma unroll
        for (int q = 0; q < 2; q++) {
            int idx = q * 256 + tid;
            int r = idx >> 7, c = idx & 127;
            g_Wc[l][(r4 * 4 + r) * 128 + c] = reduce8(sPart, idx);
        }
    } else if (rb == 96) {
        for (int idx = tid; idx < 384; idx += 256) {
            int l = idx >> 7, c = idx & 127;
            const float* e2 = eb2 + l * 128;
            const float* W = nw1 + l * 32768 + 16384 + c;
            float s = 0.f;
#pragma unroll 8
            for (int m = 0; m < 128; m++) s = fmaf(e2[m], W[m * 128], s);
            g_cb[l][c] = s;
        }
    }
    bar_arrive(0, tid, sBarT);

    // ---- CTA-local setup (overlapped with other CTAs' Wc work) ----
    sX[tid] = nf[rb * 512 + tid];
    sX[tid + 256] = nf[rb * 512 + 256 + tid];
    const float* adjb = adj + (size_t)(b * 256 + il0) * 256;
#pragma unroll
    for (int e = 0; e < 4; e++) {
        int idx = e * 256 + tid;
        int r = idx >> 8, j = idx & 255;
        float v = adjb[r * 256 + j];
        *(float2*)(sAdj2 + j * 8 + 2 * r) = make_float2(v, v);
    }
    if (w < 4) {
        float s = 0.f;
        const float* row = adjb + w * 256;
#pragma unroll
        for (int j = lane; j < 256; j += 32) s += row[j];
#pragma unroll
        for (int o = 16; o; o >>= 1) s += __shfl_xor_sync(~0u, s, o);
        if (!lane) s_rs[w] = s;
    }
    stage32(b0, ew1 + 16384, tid);          // l0 ew1b.h0
    stage32(b1, ew1 + 16384 + 8192, tid);   // l0 ew1b.h1
    bar_wait(0, tid, sBarT);
    // invariant entering each layer: pending = [b0 <- ew1b.h0, b1 <- ew1b.h1]

    // ================= layers =================
    for (int l = 0; l < L_; l++) {
        float* Pbuf = g_P[l & 1];
        const float* ew1l = ew1 + l * 32768;

#pragma unroll
        for (int q = 0; q < 2; q++) {              // sX -> dup'd sATs
            int idx = q * 256 + tid;
            int r = idx >> 7, k = idx & 127;
            float v = sX[idx];
            *(float2*)(sATs + k * 10 + 2 * r) = make_float2(v, v);
        }
        cpa_wait1();  __syncthreads();             // eb.h0 in

        // ---- Pj = x @ ew1b ----
        {
            u64 acc[4][2] = {};
            gemm_half(sATs, b0, lane, w, 0, acc);
            __syncthreads();
            stage32(b0, ew1l, tid);                // ea.h0   [eb.h1, ea.h0]
            cpa_wait1();  __syncthreads();         // eb.h1 in
            gemm_half(sATs, b1, lane, w, 1, acc);
            store_part4(sPart, acc, lane, w);
            __syncthreads();
            stage32(b1, ew1l + 8192, tid);         // ea.h1   [ea.h0, ea.h1]
#pragma unroll
            for (int q = 0; q < 2; q++) {
                int idx = q * 256 + tid;
                int r = idx >> 7, c = idx & 127;
                Pbuf[(rb * 4 + r) * 128 + c] = reduce8(sPart, idx);
            }
        }
        bar_arrive(1 + l, tid, sBarT);             // Pj published

        // ---- Pi = x @ ew1a + eb1 (hidden behind barrier) ----
        {
            cpa_wait1();  __syncthreads();         // ea.h0 in
            u64 acc[4][2] = {};
            gemm_half(sATs, b0, lane, w, 0, acc);
            __syncthreads();
            stage32(b0, nw1 + l * 32768, tid);     // na.h0   [ea.h1, na.h0]
            cpa_wait1();  __syncthreads();         // ea.h1 in
            gemm_half(sATs, b1, lane, w, 1, acc);
            store_part4(sPart, acc, lane, w);
            __syncthreads();
            stage32(b1, nw1 + l * 32768 + 8192, tid);  // na.h1  [na.h0, na.h1]
#pragma unroll
            for (int q = 0; q < 2; q++) {
                int idx = q * 256 + tid;
                int c = idx & 127;
                sPi[idx] = reduce8(sPart, idx) + eb1[l * 128 + c];
            }
        }

        // ---- Pn = x @ nw1a + nb1; Pj staging starts after bar_wait ----
        {
            cpa_wait1();  __syncthreads();         // na.h0 in
            u64 acc[4][2] = {};
            gemm_half(sATs, b0, lane, w, 0, acc);
            __syncthreads();
            bar_wait(1 + l, tid, sBarT);           // all Pj visible; b0 free
            stage32(b0, Pbuf + b * 32768, tid);    // Pj.q0   [na.h1, q0]
            cpa_wait1();  __syncthreads();         // na.h1 in
            gemm_half(sATs, b1, lane, w, 1, acc);
            store_part4(sPart, acc, lane, w);
            __syncthreads();
            stage32(b1, Pbuf + b * 32768 + 8192, tid);  // Pj.q1  [q0, q1]
#pragma unroll
            for (int q = 0; q < 2; q++) {
                int idx = q * 256 + tid;
                int c = idx & 127;
                sPn[idx] = reduce8(sPart, idx) + nb1[l * 128 + c];
            }
        }

        // ---- agg over 4 Pj quarters (acc persists) ----
        {
            cpa_wait1();  __syncthreads();         // q0 in
            u64 xi[4][2], aacc[4][2] = {};
#pragma unroll
            for (int q = 0; q < 4; q++) {
                ulonglong2 v = *(const ulonglong2*)(sPi + q * 128 + lane * 4);
                xi[q][0] = v.x; xi[q][1] = v.y;
            }
            agg_q(b0, sAdj2, xi, aacc, lane, w);
            __syncthreads();
            stage32(b0, Pbuf + b * 32768 + 16384, tid);   // Pj.q2  [q1, q2]
            cpa_wait1();  __syncthreads();         // q1 in
            agg_q(b1, sAdj2 + 64 * 8, xi, aacc, lane, w);
            __syncthreads();
            stage32(b1, Pbuf + b * 32768 + 24576, tid);   // Pj.q3  [q2, q3]
            cpa_wait1();  __syncthreads();         // q2 in
            agg_q(b0, sAdj2 + 128 * 8, xi, aacc, lane, w);
            __syncthreads();
            stage32(b0, g_Wc[l], tid);                    // Wc.h0  [q3, Wc.h0]
            cpa_wait1();  __syncthreads();         // q3 in
            agg_q(b1, sAdj2 + 192 * 8, xi, aacc, lane, w);
            store_part4(sPart, aacc, lane, w);
            __syncthreads();
            stage32(b1, g_Wc[l] + 8192, tid);             // Wc.h1  [Wc.h0, Wc.h1]
#pragma unroll
            for (int q = 0; q < 2; q++) {          // reduce agg -> dup'd sATs
                int idx = q * 256 + tid;
                int r = idx >> 7, c = idx & 127;
                float v = reduce8(sPart, idx);
                *(float2*)(sATs + c * 10 + 2 * r) = make_float2(v, v);
            }
        }

        // ---- nh = relu(Pn + agg@Wc + rs*cb) ----
        {
            cpa_wait1();  __syncthreads();         // Wc.h0 in
            u64 acc[4][2] = {};
            gemm_half(sATs, b0, lane, w, 0, acc);
            __syncthreads();
            stage32(b0, nw2 + l * 16384, tid);     // nw2.h0  [Wc.h1, nw2.h0]
            cpa_wait1();  __syncthreads();         // Wc.h1 in
            gemm_half(sATs, b1, lane, w, 1, acc);
            store_part4(sPart, acc, lane, w);
            __syncthreads();
            stage32(b1, nw2 + l * 16384 + 8192, tid);  // nw2.h1  [nw2.h0, nw2.h1]
#pragma unroll
            for (int q = 0; q < 2; q++) {
                int idx = q * 256 + tid;
                int r = idx >> 7, c = idx & 127;
                float v = reduce8(sPart, idx) + sPn[idx] + s_rs[r] * g_cb[l][c];
                v = fmaxf(v, 0.f);
                *(float2*)(sNTs + c * 10 + 2 * r) = make_float2(v, v);
            }
        }

        // ---- x += nh @ nw2 + nb2 ----
        {
            const float* ebn = ew1 + ((l + 1 < L_) ? (l + 1) : 0) * 32768 + 16384;
            cpa_wait1();  __syncthreads();         // nw2.h0 in
            u64 acc[4][2] = {};
            gemm_half(sNTs, b0, lane, w, 0, acc);
            __syncthreads();
            stage32(b0, ebn, tid);                 // next eb.h0  [nw2.h1, eb.h0]
            cpa_wait1();  __syncthreads();         // nw2.h1 in
            gemm_half(sNTs, b1, lane, w, 1, acc);
            store_part4(sPart, acc, lane, w);
            __syncthreads();
            stage32(b1, ebn + 8192, tid);          // next eb.h1  [eb.h0, eb.h1]
#pragma unroll
            for (int q = 0; q < 2; q++) {
                int idx = q * 256 + tid;
                int c = idx & 127;
                float v = sX[idx] + reduce8(sPart, idx) + nb2[l * 128 + c];
                sX[idx] = v;
                if (l == L_ - 1) x[rb * 512 + idx] = v;
            }
            __syncthreads();   // sX/sPart stable before next layer
        }
    }
    cpa_wait0();
}

// ---------------- launch ----------------
extern "C" void kernel_launch(void* const* d_in, const int* in_sizes, int n_in,
                              void* d_out, int out_size) {
    const float* nf  = (const float*)d_in[0];
    const float* adj = (const float*)d_in[1];
    const float* ew1 = (const float*)d_in[2];
    const float* eb1 = (const float*)d_in[3];
    const float* ew2 = (const float*)d_in[4];
    const float* eb2 = (const float*)d_in[5];
    const float* nw1 = (const float*)d_in[6];
    const float* nb1 = (const float*)d_in[7];
    const float* nw2 = (const float*)d_in[8];
    const float* nb2 = (const float*)d_in[9];
    float* x = (float*)d_out;

    const int SMEM = SMEM_FLOATS * 4;   // 106516 B -> 2 CTAs/SM
    cudaFuncSetAttribute(k_main, cudaFuncAttributeMaxDynamicSharedMemorySize, SMEM);
    k_main<<<NB, NT, SMEM>>>(x, nf, adj, ew1, eb1, ew2, eb2, nw1, nb1, nw2, nb2);
}

// round 11
// speedup vs baseline: 1.0711x; 1.0711x over previous
#include <cuda_runtime.h>
#include <cstdint>

typedef unsigned long long u64;
#define DEV static __device__ __forceinline__

static constexpr int L_ = 3;
static constexpr int NB = 128;   // 128 CTAs, 8 rows each
static constexpr int NT = 512;   // 16 warps

// ---------------- device globals ----------------
__device__ float g_P[2][1024 * 128];   // double-buffered Pj
__device__ float g_Wc[L_][128 * 128];  // ew2 @ nw1b
__device__ float g_cb[L_][128];        // eb2 @ nw1b
__device__ unsigned g_bar[4];          // monotonic barrier counters (replay-safe)

// ---------------- f32x2 helpers ----------------
DEV u64 pk(float lo, float hi) {
    u64 r; asm("mov.b64 %0,{%1,%2};" : "=l"(r) : "f"(lo), "f"(hi)); return r;
}
DEV void upk(u64 v, float& lo, float& hi) {
    asm("mov.b64 {%0,%1},%2;" : "=f"(lo), "=f"(hi) : "l"(v));
}
DEV u64 add2(u64 a, u64 b) {
    u64 r; asm("add.rn.f32x2 %0,%1,%2;" : "=l"(r) : "l"(a), "l"(b)); return r;
}
DEV u64 fma2(u64 a, u64 b, u64 c) {
    u64 r; asm("fma.rn.f32x2 %0,%1,%2,%3;" : "=l"(r) : "l"(a), "l"(b), "l"(c)); return r;
}
DEV u64 relu2(u64 v) {
    float lo, hi; upk(v, lo, hi);
    return pk(fmaxf(lo, 0.f), fmaxf(hi, 0.f));
}

// ---------------- cp.async helpers ----------------
DEV void cpa16(void* dst, const void* src) {
    unsigned d = (unsigned)__cvta_generic_to_shared(dst);
    asm volatile("cp.async.cg.shared.global [%0],[%1],16;" :: "r"(d), "l"(src) : "memory");
}
DEV void cpa_commit() { asm volatile("cp.async.commit_group;" ::: "memory"); }
DEV void cpa_wait0() { asm volatile("cp.async.wait_group 0;" ::: "memory"); }
DEV void cpa_wait1() { asm volatile("cp.async.wait_group 1;" ::: "memory"); }

// stage 64KB (16384 floats) with 512 threads, one commit group
DEV void stage64(float* dst, const float* src, int tid) {
#pragma unroll
    for (int i = 0; i < 8; i++)
        cpa16(dst + (i * 512 + tid) * 4, src + (i * 512 + tid) * 4);
    cpa_commit();
}

// ---------------- split grid barrier (monotonic counters; replay-safe) ----------------
DEV unsigned ld_acq(const unsigned* p) {
    unsigned v;
    asm volatile("ld.acquire.gpu.global.u32 %0,[%1];" : "=r"(v) : "l"(p) : "memory");
    return v;
}
DEV void bar_arrive(int bidx, int tid, unsigned* sT) {
    __syncthreads();
    if (tid == 0) {
        __threadfence();
        unsigned t = atomicAdd(&g_bar[bidx], 1u);
        *sT = (t / (unsigned)NB + 1u) * (unsigned)NB;
    }
}
DEV void bar_wait(int bidx, int tid, unsigned* sT) {
    __syncthreads();
    if (tid == 0) {
        unsigned target = *sT;
        while (ld_acq(&g_bar[bidx]) < target) { __nanosleep(64); }
        __threadfence();
    }
    __syncthreads();
}

// ---------------- r=4 k-split-8 GEMM (W in smem) ----------------
// warp = (rg = w&1, kq = w>>1 of 8, 16 k each), lane = 4 cols.
// dup'd A layout: ATs[k*20 + 2r] = ATs[k*20+2r+1] = A[r][k]
DEV void gemm_r4k8(const float* __restrict__ ATs, const float* __restrict__ Wsm,
                   int lane, int rg, int kq, u64 acc[4][2]) {
    const float* ap = ATs + kq * 16 * 20 + rg * 8;
    const float* wp = Wsm + kq * 16 * 128 + lane * 4;
#pragma unroll
    for (int k = 0; k < 16; k++) {
        ulonglong2 a01 = *(const ulonglong2*)(ap + k * 20);
        ulonglong2 a23 = *(const ulonglong2*)(ap + k * 20 + 4);
        ulonglong2 wv = *(const ulonglong2*)(wp + k * 128);
        acc[0][0] = fma2(a01.x, wv.x, acc[0][0]);
        acc[0][1] = fma2(a01.x, wv.y, acc[0][1]);
        acc[1][0] = fma2(a01.y, wv.x, acc[1][0]);
        acc[1][1] = fma2(a01.y, wv.y, acc[1][1]);
        acc[2][0] = fma2(a23.x, wv.x, acc[2][0]);
        acc[2][1] = fma2(a23.x, wv.y, acc[2][1]);
        acc[3][0] = fma2(a23.y, wv.x, acc[3][0]);
        acc[3][1] = fma2(a23.y, wv.y, acc[3][1]);
    }
}

// ---------------- merged 8x256 GEMM: warp=(cg2,rg2,kq4), 32 k each ----------------
DEV void gemm_m(const float* __restrict__ ATs, const float* __restrict__ Wsm,
                int lane, int rg, int kq, u64 acc[4][2]) {
    const float* ap = ATs + kq * 32 * 20 + rg * 8;
    const float* wp = Wsm + kq * 32 * 128 + lane * 4;
#pragma unroll 16
    for (int k = 0; k < 32; k++) {
        ulonglong2 a01 = *(const ulonglong2*)(ap + k * 20);
        ulonglong2 a23 = *(const ulonglong2*)(ap + k * 20 + 4);
        ulonglong2 wv = *(const ulonglong2*)(wp + k * 128);
        acc[0][0] = fma2(a01.x, wv.x, acc[0][0]);
        acc[0][1] = fma2(a01.x, wv.y, acc[0][1]);
        acc[1][0] = fma2(a01.y, wv.x, acc[1][0]);
        acc[1][1] = fma2(a01.y, wv.y, acc[1][1]);
        acc[2][0] = fma2(a23.x, wv.x, acc[2][0]);
        acc[2][1] = fma2(a23.x, wv.y, acc[2][1]);
        acc[3][0] = fma2(a23.y, wv.x, acc[3][0]);
        acc[3][1] = fma2(a23.y, wv.y, acc[3][1]);
    }
}

DEV void store_part8(float* sPart, const u64 acc[4][2], int lane, int rg, int kq) {
    float* o = sPart + kq * 1024 + rg * 4 * 128 + lane * 4;
#pragma unroll
    for (int r = 0; r < 4; r++) {
        float v0, v1, v2, v3;
        upk(acc[r][0], v0, v1); upk(acc[r][1], v2, v3);
        *(float4*)(o + r * 128) = make_float4(v0, v1, v2, v3);
    }
}

DEV float reduce8(const float* __restrict__ sPart, int idx) {
    float v = 0.f;
#pragma unroll
    for (int p = 0; p < 8; p++) v += sPart[p * 1024 + idx];
    return v;
}

// ---------------- agg via direct LDG.cg: warp=(ig2,jq8), 4i x 4d, 32 j ----------
// Pjb: global base of this batch's Pj slab (visible via barrier fence+acquire).
// .cg bypasses L1 -> no stale-line hazard on the double-buffered g_P.
DEV void agg_ldg(const float* __restrict__ Pjb, const float* __restrict__ sAdj2,
                 const u64 xi[4][2], u64 acc[4][2], int lane, int ig, int jq) {
    const float* pj = Pjb + jq * 32 * 128 + lane * 4;
    const float* ad = sAdj2 + jq * 32 * 16 + ig * 8;
#pragma unroll 8
    for (int jj = 0; jj < 32; jj++) {
        ulonglong2 xj = __ldcg((const ulonglong2*)(pj + jj * 128));
        ulonglong2 a01 = *(const ulonglong2*)(ad + jj * 16);
        ulonglong2 a23 = *(const ulonglong2*)(ad + jj * 16 + 4);
        u64 t;
        t = relu2(add2(xi[0][0], xj.x)); acc[0][0] = fma2(t, a01.x, acc[0][0]);
        t = relu2(add2(xi[0][1], xj.y)); acc[0][1] = fma2(t, a01.x, acc[0][1]);
        t = relu2(add2(xi[1][0], xj.x)); acc[1][0] = fma2(t, a01.y, acc[1][0]);
        t = relu2(add2(xi[1][1], xj.y)); acc[1][1] = fma2(t, a01.y, acc[1][1]);
        t = relu2(add2(xi[2][0], xj.x)); acc[2][0] = fma2(t, a23.x, acc[2][0]);
        t = relu2(add2(xi[2][1], xj.y)); acc[2][1] = fma2(t, a23.x, acc[2][1]);
        t = relu2(add2(xi[3][0], xj.x)); acc[3][0] = fma2(t, a23.y, acc[3][0]);
        t = relu2(add2(xi[3][1], xj.y)); acc[3][1] = fma2(t, a23.y, acc[3][1]);
    }
}

// ---------------- smem layout (floats) ----------------
// b0 0 (16384) | b1 16384 (16384) | sPart 32768 (8192) | sATs 40960 (2560)
// sNTs 43520 (2560) | sPi 46080 (1024) | sPn 47104 (1024) | sAdj2 48128 (4096)
// s_rs 52224 (8) | sX 52232 (1024) | sBarT 53256 (1 uint)
static constexpr int SMEM_FLOATS = 53260;   // 213040 B

__global__ void __launch_bounds__(NT, 1) k_main(
    float* __restrict__ x, const float* __restrict__ nf, const float* __restrict__ adj,
    const float* __restrict__ ew1, const float* __restrict__ eb1,
    const float* __restrict__ ew2, const float* __restrict__ eb2,
    const float* __restrict__ nw1, const float* __restrict__ nb1,
    const float* __restrict__ nw2, const float* __restrict__ nb2) {
    extern __shared__ float sm[];
    float* b0 = sm;
    float* b1 = sm + 16384;
    float* sPart = sm + 32768;
    float* sATs = sm + 40960;
    float* sNTs = sm + 43520;
    float* sPi = sm + 46080;
    float* sPn = sm + 47104;
    float* sAdj2 = sm + 48128;
    float* s_rs = sm + 52224;
    float* sX = sm + 52232;
    unsigned* sBarT = (unsigned*)(sm + 53256);

    int tid = threadIdx.x, lane = tid & 31, w = tid >> 5;
    int rb = blockIdx.x;        // rows rb*8 .. rb*8+7
    int b = rb >> 5;            // batch
    int il0 = (rb & 31) * 8;    // local i base in batch
    int rg = w & 1, kq = w >> 1;              // r4k8 roles
    int mcg = w & 1, mrg = (w >> 1) & 1, mkq = w >> 2;   // merged-GEMM roles
    int ig = w & 1, jq = w >> 1;              // agg roles
    int rr = tid >> 7, cc = tid & 127;        // reduce/epilogue roles

    // ================= setup: produce Wc/cb, arrive, local setup, wait ==========
    if (rb < 48) {   // Wc[l] = ew2[l] @ nw1b[l]
        int l = rb / 16, r8 = rb % 16;
        stage64(b0, nw1 + l * 32768 + 16384, tid);
#pragma unroll
        for (int q = 0; q < 2; q++) {
            int idx = q * 512 + tid;
            int r = idx >> 7, k = idx & 127;
            float v = ew2[l * 16384 + (r8 * 8 + r) * 128 + k];
            *(float2*)(sATs + k * 20 + 2 * r) = make_float2(v, v);
        }
        cpa_wait0();
        __syncthreads();
        u64 acc[4][2] = {};
        gemm_r4k8(sATs, b0, lane, rg, kq, acc);
        store_part8(sPart, acc, lane, rg, kq);
        __syncthreads();
#pragma unroll
        for (int q = 0; q < 2; q++) {
            int idx = q * 512 + tid;
            g_Wc[l][(r8 * 8 + rr + q * 4) * 128 + cc] = reduce8(sPart, idx);
        }
    } else if (rb == 48) {
        if (tid < 384) {
            int l = tid >> 7, c = tid & 127;
            const float* e2 = eb2 + l * 128;
            const float* W = nw1 + l * 32768 + 16384 + c;
            float s = 0.f;
#pragma unroll 8
            for (int m = 0; m < 128; m++) s = fmaf(e2[m], W[m * 128], s);
            g_cb[l][c] = s;
        }
    }
    bar_arrive(0, tid, sBarT);

    // ---- CTA-local setup, overlapped with other CTAs' Wc work ----
#pragma unroll
    for (int q = 0; q < 2; q++) sX[q * 512 + tid] = nf[rb * 1024 + q * 512 + tid];
    const float* adjb = adj + (size_t)(b * 256 + il0) * 256;
#pragma unroll
    for (int e = 0; e < 4; e++) {
        int idx = e * 512 + tid;
        int r = idx >> 8, j = idx & 255;
        float v = adjb[r * 256 + j];
        *(float2*)(sAdj2 + j * 16 + 2 * r) = make_float2(v, v);
    }
    if (w < 8) {
        float s = 0.f;
        const float* row = adjb + w * 256;
#pragma unroll
        for (int j = lane; j < 256; j += 32) s += row[j];
#pragma unroll
        for (int o = 16; o; o >>= 1) s += __shfl_xor_sync(~0u, s, o);
        if (!lane) s_rs[w] = s;
    }
    stage64(b0, ew1 + 16384, tid);   // ew1b layer 0   [1 pending]
    bar_wait(0, tid, sBarT);
    // invariant entering each layer: pending = [b0 <- ew1b]

    // ================= layers =================
    for (int l = 0; l < L_; l++) {
        float* Pbuf = g_P[l & 1];
        const float* ew1l = ew1 + l * 32768;

        stage64(b1, ew1l, tid);                    // ew1a    [ew1b, ew1a]
#pragma unroll
        for (int q = 0; q < 2; q++) {              // sX -> dup'd sATs
            int idx = q * 512 + tid;
            int r = idx >> 7, k = idx & 127;
            float v = sX[idx];
            *(float2*)(sATs + k * 20 + 2 * r) = make_float2(v, v);
        }
        cpa_wait1();        // ew1b (b0) landed
        __syncthreads();

        // ---- Pj = x @ ew1b -> global, then ARRIVE ----
        {
            u64 acc[4][2] = {};
            gemm_r4k8(sATs, b0, lane, rg, kq, acc);
            store_part8(sPart, acc, lane, rg, kq);
            __syncthreads();                       // b0 reads done
            stage64(b0, nw1 + l * 32768, tid);     // nw1a    [ew1a, nw1a]
#pragma unroll
            for (int q = 0; q < 2; q++) {
                int idx = q * 512 + tid;
                Pbuf[(rb * 8 + rr + q * 4) * 128 + cc] = reduce8(sPart, idx);
            }
        }
        bar_arrive(1 + l, tid, sBarT);             // Pj published

        cpa_wait0();        // ew1a (b1) + nw1a (b0) landed
        __syncthreads();

        // ---- merged: [Pi|Pn] = x @ [ew1a | nw1a] + [eb1|nb1] (hidden behind barrier) ----
        {
            u64 acc[4][2] = {};
            gemm_m(sATs, mcg ? b0 : b1, lane, mrg, mkq, acc);
            {   // store to sPart[kq][8r][256c]
                float* o = sPart + mkq * 2048 + mrg * 4 * 256 + mcg * 128 + lane * 4;
#pragma unroll
                for (int r = 0; r < 4; r++) {
                    float v0, v1, v2, v3;
                    upk(acc[r][0], v0, v1); upk(acc[r][1], v2, v3);
                    *(float4*)(o + r * 256) = make_float4(v0, v1, v2, v3);
                }
            }
            __syncthreads();
#pragma unroll
            for (int q = 0; q < 4; q++) {
                int idx = q * 512 + tid;
                int r = idx >> 8, c = idx & 255;
                float v = 0.f;
#pragma unroll
                for (int p = 0; p < 4; p++) v += sPart[p * 2048 + idx];
                if (c < 128) sPi[r * 128 + c] = v + eb1[l * 128 + c];
                else         sPn[r * 128 + c - 128] = v + nb1[l * 128 + (c - 128)];
            }
        }
        bar_wait(1 + l, tid, sBarT);   // all Pj visible; b0,b1 free

        // ---- overlap weight staging with the whole agg phase ----
        stage64(b0, g_Wc[l], tid);                 // Wc    [Wc]
        stage64(b1, nw2 + l * 16384, tid);         // nw2   [Wc, nw2]
        __syncthreads();   // sPi/sPn complete before agg reads them

        // ---- agg: direct LDG.cg from Pbuf, no smem staging ----
        {
            u64 xi[4][2], aacc[4][2] = {};
#pragma unroll
            for (int q = 0; q < 4; q++) {
                ulonglong2 v = *(const ulonglong2*)(sPi + (ig * 4 + q) * 128 + lane * 4);
                xi[q][0] = v.x; xi[q][1] = v.y;
            }
            agg_ldg(Pbuf + b * 32768, sAdj2, xi, aacc, lane, ig, jq);
            float* o = sPart + jq * 1024 + ig * 4 * 128 + lane * 4;
#pragma unroll
            for (int q = 0; q < 4; q++) {
                float v0, v1, v2, v3;
                upk(aacc[q][0], v0, v1); upk(aacc[q][1], v2, v3);
                *(float4*)(o + q * 128) = make_float4(v0, v1, v2, v3);
            }
        }
        __syncthreads();                            // sPart ready
#pragma unroll
        for (int q = 0; q < 2; q++) {               // reduce agg -> dup'd sATs
            int idx = q * 512 + tid;
            float v = reduce8(sPart, idx);
            *(float2*)(sATs + cc * 20 + 2 * (rr + q * 4)) = make_float2(v, v);
        }
        cpa_wait1();        // Wc (b0) landed
        __syncthreads();

        // ---- nh = relu(Pn + agg@Wc + rs*cb) ----
        {
            u64 acc[4][2] = {};
            gemm_r4k8(sATs, b0, lane, rg, kq, acc);
            store_part8(sPart, acc, lane, rg, kq);
            __syncthreads();                        // b0 free
            stage64(b0, ew1 + (l + 1 < L_ ? l + 1 : 0) * 32768 + 16384, tid);  // next ew1b [nw2, ew1b']
            float cbv = g_cb[l][cc];
#pragma unroll
            for (int q = 0; q < 2; q++) {
                int idx = q * 512 + tid;
                int r = rr + q * 4;
                float v = reduce8(sPart, idx) + sPn[r * 128 + cc] + s_rs[r] * cbv;
                v = fmaxf(v, 0.f);
                *(float2*)(sNTs + cc * 20 + 2 * r) = make_float2(v, v);
            }
            cpa_wait1();    // nw2 (b1) landed
            __syncthreads();
        }

        // ---- x += nh @ nw2 + nb2 ----
        {
            u64 acc[4][2] = {};
            gemm_r4k8(sNTs, b1, lane, rg, kq, acc);
            store_part8(sPart, acc, lane, rg, kq);
            __syncthreads();
            float bv = nb2[l * 128 + cc];
#pragma unroll
            for (int q = 0; q < 2; q++) {
                int idx = q * 512 + tid;
                float v = sX[idx] + reduce8(sPart, idx) + bv;
                sX[idx] = v;
                if (l == L_ - 1) x[rb * 1024 + idx] = v;
            }
            __syncthreads();
        }
        // loop invariant restored: pending = [b0 <- next ew1b]
    }
    cpa_wait0();
}

// ---------------- launch ----------------
extern "C" void kernel_launch(void* const* d_in, const int* in_sizes, int n_in,
                              void* d_out, int out_size) {
    const float* nf  = (const float*)d_in[0];
    const float* adj = (const float*)d_in[1];
    const float* ew1 = (const float*)d_in[2];
    const float* eb1 = (const float*)d_in[3];
    const float* ew2 = (const float*)d_in[4];
    const float* eb2 = (const float*)d_in[5];
    const float* nw1 = (const float*)d_in[6];
    const float* nb1 = (const float*)d_in[7];
    const float* nw2 = (const float*)d_in[8];
    const float* nb2 = (const float*)d_in[9];
    float* x = (float*)d_out;

    const int SMEM = SMEM_FLOATS * 4;   // 213040 B
    cudaFuncSetAttribute(k_main, cudaFuncAttributeMaxDynamicSharedMemorySize, SMEM);
    k_main<<<NB, NT, SMEM>>>(x, nf, adj, ew1, eb1, ew2, eb2, nw1, nb1, nw2, nb2);
}

// round 12
// speedup vs baseline: 1.1188x; 1.0446x over previous
#include <cuda_runtime.h>
#include <cstdint>

typedef unsigned long long u64;
#define DEV static __device__ __forceinline__

static constexpr int L_ = 3;
static constexpr int NB = 128;   // 128 CTAs, 8 rows each
static constexpr int NT = 512;   // 16 warps

// ---------------- device globals ----------------
__device__ float g_P[2][1024 * 128];   // double-buffered Pj
__device__ float g_Wc[L_][128 * 128];  // ew2 @ nw1b
__device__ float g_cb[L_][128];        // eb2 @ nw1b
__device__ unsigned g_bar[4];          // monotonic barrier counters (replay-safe)

// ---------------- f32x2 helpers ----------------
DEV u64 pk(float lo, float hi) {
    u64 r; asm("mov.b64 %0,{%1,%2};" : "=l"(r) : "f"(lo), "f"(hi)); return r;
}
DEV void upk(u64 v, float& lo, float& hi) {
    asm("mov.b64 {%0,%1},%2;" : "=f"(lo), "=f"(hi) : "l"(v));
}
DEV u64 add2(u64 a, u64 b) {
    u64 r; asm("add.rn.f32x2 %0,%1,%2;" : "=l"(r) : "l"(a), "l"(b)); return r;
}
DEV u64 fma2(u64 a, u64 b, u64 c) {
    u64 r; asm("fma.rn.f32x2 %0,%1,%2,%3;" : "=l"(r) : "l"(a), "l"(b), "l"(c)); return r;
}
DEV u64 relu2(u64 v) {
    float lo, hi; upk(v, lo, hi);
    return pk(fmaxf(lo, 0.f), fmaxf(hi, 0.f));
}

// ---------------- split grid barrier (monotonic counters; replay-safe) ----------------
DEV unsigned ld_acq(const unsigned* p) {
    unsigned v;
    asm volatile("ld.acquire.gpu.global.u32 %0,[%1];" : "=r"(v) : "l"(p) : "memory");
    return v;
}
DEV void bar_arrive(int bidx, int tid, unsigned* sT) {
    __syncthreads();
    if (tid == 0) {
        __threadfence();
        unsigned t = atomicAdd(&g_bar[bidx], 1u);
        *sT = (t / (unsigned)NB + 1u) * (unsigned)NB;
    }
}
DEV void bar_wait(int bidx, int tid, unsigned* sT) {
    __syncthreads();
    if (tid == 0) {
        unsigned target = *sT;
        while (ld_acq(&g_bar[bidx]) < target) { __nanosleep(64); }
        __threadfence();
    }
    __syncthreads();
}

// ---------------- r=4 k-split-8 GEMM, W direct from global via __ldg --------------
// warp = (rg = w&1, kq = w>>1 of 8, 16 k each), lane = 4 cols.
// dup'd A layout: ATs[k*20 + 2r] = ATs[k*20+2r+1] = A[r][k]
DEV void gemm_g(const float* __restrict__ ATs, const float* __restrict__ W,
                int lane, int rg, int kq, u64 acc[4][2]) {
    const float* ap = ATs + kq * 16 * 20 + rg * 8;
    const float* wp = W + kq * 16 * 128 + lane * 4;
#pragma unroll
    for (int k = 0; k < 16; k++) {
        ulonglong2 wv = __ldg((const ulonglong2*)(wp + k * 128));
        ulonglong2 a01 = *(const ulonglong2*)(ap + k * 20);
        ulonglong2 a23 = *(const ulonglong2*)(ap + k * 20 + 4);
        acc[0][0] = fma2(a01.x, wv.x, acc[0][0]);
        acc[0][1] = fma2(a01.x, wv.y, acc[0][1]);
        acc[1][0] = fma2(a01.y, wv.x, acc[1][0]);
        acc[1][1] = fma2(a01.y, wv.y, acc[1][1]);
        acc[2][0] = fma2(a23.x, wv.x, acc[2][0]);
        acc[2][1] = fma2(a23.x, wv.y, acc[2][1]);
        acc[3][0] = fma2(a23.y, wv.x, acc[3][0]);
        acc[3][1] = fma2(a23.y, wv.y, acc[3][1]);
    }
}

// ---------------- merged 8x256 GEMM: warp=(cg2,rg2,kq4), 32 k each, W via __ldg ----
DEV void gemm_m_g(const float* __restrict__ ATs, const float* __restrict__ W,
                  int lane, int rg, int kq, u64 acc[4][2]) {
    const float* ap = ATs + kq * 32 * 20 + rg * 8;
    const float* wp = W + kq * 32 * 128 + lane * 4;
#pragma unroll 16
    for (int k = 0; k < 32; k++) {
        ulonglong2 wv = __ldg((const ulonglong2*)(wp + k * 128));
        ulonglong2 a01 = *(const ulonglong2*)(ap + k * 20);
        ulonglong2 a23 = *(const ulonglong2*)(ap + k * 20 + 4);
        acc[0][0] = fma2(a01.x, wv.x, acc[0][0]);
        acc[0][1] = fma2(a01.x, wv.y, acc[0][1]);
        acc[1][0] = fma2(a01.y, wv.x, acc[1][0]);
        acc[1][1] = fma2(a01.y, wv.y, acc[1][1]);
        acc[2][0] = fma2(a23.x, wv.x, acc[2][0]);
        acc[2][1] = fma2(a23.x, wv.y, acc[2][1]);
        acc[3][0] = fma2(a23.y, wv.x, acc[3][0]);
        acc[3][1] = fma2(a23.y, wv.y, acc[3][1]);
    }
}

DEV void store_part8(float* sPart, const u64 acc[4][2], int lane, int rg, int kq) {
    float* o = sPart + kq * 1024 + rg * 4 * 128 + lane * 4;
#pragma unroll
    for (int r = 0; r < 4; r++) {
        float v0, v1, v2, v3;
        upk(acc[r][0], v0, v1); upk(acc[r][1], v2, v3);
        *(float4*)(o + r * 128) = make_float4(v0, v1, v2, v3);
    }
}

DEV float reduce8(const float* __restrict__ sPart, int idx) {
    float v = 0.f;
#pragma unroll
    for (int p = 0; p < 8; p++) v += sPart[p * 1024 + idx];
    return v;
}

// ---------------- agg via direct LDG.cg: warp=(ig2,jq8), 4i x 4d, 32 j ----------
DEV void agg_ldg(const float* __restrict__ Pjb, const float* __restrict__ sAdj2,
                 const u64 xi[4][2], u64 acc[4][2], int lane, int ig, int jq) {
    const float* pj = Pjb + jq * 32 * 128 + lane * 4;
    const float* ad = sAdj2 + jq * 32 * 16 + ig * 8;
#pragma unroll 8
    for (int jj = 0; jj < 32; jj++) {
        ulonglong2 xj = __ldcg((const ulonglong2*)(pj + jj * 128));
        ulonglong2 a01 = *(const ulonglong2*)(ad + jj * 16);
        ulonglong2 a23 = *(const ulonglong2*)(ad + jj * 16 + 4);
        u64 t;
        t = relu2(add2(xi[0][0], xj.x)); acc[0][0] = fma2(t, a01.x, acc[0][0]);
        t = relu2(add2(xi[0][1], xj.y)); acc[0][1] = fma2(t, a01.x, acc[0][1]);
        t = relu2(add2(xi[1][0], xj.x)); acc[1][0] = fma2(t, a01.y, acc[1][0]);
        t = relu2(add2(xi[1][1], xj.y)); acc[1][1] = fma2(t, a01.y, acc[1][1]);
        t = relu2(add2(xi[2][0], xj.x)); acc[2][0] = fma2(t, a23.x, acc[2][0]);
        t = relu2(add2(xi[2][1], xj.y)); acc[2][1] = fma2(t, a23.x, acc[2][1]);
        t = relu2(add2(xi[3][0], xj.x)); acc[3][0] = fma2(t, a23.y, acc[3][0]);
        t = relu2(add2(xi[3][1], xj.y)); acc[3][1] = fma2(t, a23.y, acc[3][1]);
    }
}

// ---------------- smem layout (floats) ----------------
// sPart 0 (8192) | sATs 8192 (2560) | sNTs 10752 (2560) | sPi 13312 (1024)
// sPn 14336 (1024) | sAdj2 15360 (4096) | s_rs 19456 (8) | sX 19464 (1024)
// sBarT 20488 (1)
static constexpr int SMEM_FLOATS = 20489;   // 81956 B

__global__ void __launch_bounds__(NT, 1) k_main(
    float* __restrict__ x, const float* __restrict__ nf, const float* __restrict__ adj,
    const float* __restrict__ ew1, const float* __restrict__ eb1,
    const float* __restrict__ ew2, const float* __restrict__ eb2,
    const float* __restrict__ nw1, const float* __restrict__ nb1,
    const float* __restrict__ nw2, const float* __restrict__ nb2) {
    extern __shared__ float sm[];
    float* sPart = sm;
    float* sATs = sm + 8192;
    float* sNTs = sm + 10752;
    float* sPi = sm + 13312;
    float* sPn = sm + 14336;
    float* sAdj2 = sm + 15360;
    float* s_rs = sm + 19456;
    float* sX = sm + 19464;
    unsigned* sBarT = (unsigned*)(sm + 20488);

    int tid = threadIdx.x, lane = tid & 31, w = tid >> 5;
    int rb = blockIdx.x;        // rows rb*8 .. rb*8+7
    int b = rb >> 5;            // batch
    int il0 = (rb & 31) * 8;    // local i base in batch
    int rg = w & 1, kq = w >> 1;              // r4k8 roles
    int mcg = w & 1, mrg = (w >> 1) & 1, mkq = w >> 2;   // merged-GEMM roles
    int ig = w & 1, jq = w >> 1;              // agg roles
    int rr = tid >> 7, cc = tid & 127;        // reduce/epilogue roles

    // ================= setup: produce Wc/cb, arrive, local setup, wait ==========
    if (rb < 48) {   // Wc[l] = ew2[l] @ nw1b[l]
        int l = rb / 16, r8 = rb % 16;
#pragma unroll
        for (int q = 0; q < 2; q++) {
            int idx = q * 512 + tid;
            int r = idx >> 7, k = idx & 127;
            float v = ew2[l * 16384 + (r8 * 8 + r) * 128 + k];
            *(float2*)(sATs + k * 20 + 2 * r) = make_float2(v, v);
        }
        __syncthreads();
        u64 acc[4][2] = {};
        gemm_g(sATs, nw1 + l * 32768 + 16384, lane, rg, kq, acc);
        store_part8(sPart, acc, lane, rg, kq);
        __syncthreads();
#pragma unroll
        for (int q = 0; q < 2; q++) {
            int idx = q * 512 + tid;
            g_Wc[l][(r8 * 8 + rr + q * 4) * 128 + cc] = reduce8(sPart, idx);
        }
    } else if (rb == 48) {
        if (tid < 384) {
            int l = tid >> 7, c = tid & 127;
            const float* e2 = eb2 + l * 128;
            const float* W = nw1 + l * 32768 + 16384 + c;
            float s = 0.f;
#pragma unroll 8
            for (int m = 0; m < 128; m++) s = fmaf(e2[m], W[m * 128], s);
            g_cb[l][c] = s;
        }
    }
    bar_arrive(0, tid, sBarT);

    // ---- CTA-local setup, overlapped with other CTAs' Wc work ----
#pragma unroll
    for (int q = 0; q < 2; q++) sX[q * 512 + tid] = nf[rb * 1024 + q * 512 + tid];
    const float* adjb = adj + (size_t)(b * 256 + il0) * 256;
#pragma unroll
    for (int e = 0; e < 4; e++) {
        int idx = e * 512 + tid;
        int r = idx >> 8, j = idx & 255;
        float v = adjb[r * 256 + j];
        *(float2*)(sAdj2 + j * 16 + 2 * r) = make_float2(v, v);
    }
    if (w < 8) {
        float s = 0.f;
        const float* row = adjb + w * 256;
#pragma unroll
        for (int j = lane; j < 256; j += 32) s += row[j];
#pragma unroll
        for (int o = 16; o; o >>= 1) s += __shfl_xor_sync(~0u, s, o);
        if (!lane) s_rs[w] = s;
    }
    bar_wait(0, tid, sBarT);

    // ================= layers =================
    for (int l = 0; l < L_; l++) {
        float* Pbuf = g_P[l & 1];
        const float* ew1l = ew1 + l * 32768;

#pragma unroll
        for (int q = 0; q < 2; q++) {              // sX -> dup'd sATs
            int idx = q * 512 + tid;
            int r = idx >> 7, k = idx & 127;
            float v = sX[idx];
            *(float2*)(sATs + k * 20 + 2 * r) = make_float2(v, v);
        }
        __syncthreads();

        // ---- Pj = x @ ew1b -> global, then ARRIVE ----
        {
            u64 acc[4][2] = {};
            gemm_g(sATs, ew1l + 16384, lane, rg, kq, acc);
            store_part8(sPart, acc, lane, rg, kq);
            __syncthreads();
#pragma unroll
            for (int q = 0; q < 2; q++) {
                int idx = q * 512 + tid;
                Pbuf[(rb * 8 + rr + q * 4) * 128 + cc] = reduce8(sPart, idx);
            }
        }
        bar_arrive(1 + l, tid, sBarT);             // Pj published

        // ---- merged: [Pi|Pn] = x @ [ew1a | nw1a] + [eb1|nb1] (hidden behind barrier) ----
        {
            __syncthreads();   // sPart consumed by Pj reduce before overwrite
            u64 acc[4][2] = {};
            gemm_m_g(sATs, mcg ? (nw1 + l * 32768) : ew1l, lane, mrg, mkq, acc);
            {   // store to sPart[kq][8r][256c]
                float* o = sPart + mkq * 2048 + mrg * 4 * 256 + mcg * 128 + lane * 4;
#pragma unroll
                for (int r = 0; r < 4; r++) {
                    float v0, v1, v2, v3;
                    upk(acc[r][0], v0, v1); upk(acc[r][1], v2, v3);
                    *(float4*)(o + r * 256) = make_float4(v0, v1, v2, v3);
                }
            }
            __syncthreads();
#pragma unroll
            for (int q = 0; q < 4; q++) {
                int idx = q * 512 + tid;
                int r = idx >> 8, c = idx & 255;
                float v = 0.f;
#pragma unroll
                for (int p = 0; p < 4; p++) v += sPart[p * 2048 + idx];
                if (c < 128) sPi[r * 128 + c] = v + eb1[l * 128 + c];
                else         sPn[r * 128 + c - 128] = v + nb1[l * 128 + (c - 128)];
            }
        }
        bar_wait(1 + l, tid, sBarT);   // all Pj visible; sPi/sPn complete (sync inside)

        // ---- agg: direct LDG.cg from Pbuf ----
        {
            u64 xi[4][2], aacc[4][2] = {};
#pragma unroll
            for (int q = 0; q < 4; q++) {
                ulonglong2 v = *(const ulonglong2*)(sPi + (ig * 4 + q) * 128 + lane * 4);
                xi[q][0] = v.x; xi[q][1] = v.y;
            }
            agg_ldg(Pbuf + b * 32768, sAdj2, xi, aacc, lane, ig, jq);
            float* o = sPart + jq * 1024 + ig * 4 * 128 + lane * 4;
#pragma unroll
            for (int q = 0; q < 4; q++) {
                float v0, v1, v2, v3;
                upk(aacc[q][0], v0, v1); upk(aacc[q][1], v2, v3);
                *(float4*)(o + q * 128) = make_float4(v0, v1, v2, v3);
            }
        }
        __syncthreads();
#pragma unroll
        for (int q = 0; q < 2; q++) {               // reduce agg -> dup'd sATs
            int idx = q * 512 + tid;
            float v = reduce8(sPart, idx);
            *(float2*)(sATs + cc * 20 + 2 * (rr + q * 4)) = make_float2(v, v);
        }
        __syncthreads();

        // ---- nh = relu(Pn + agg@Wc + rs*cb) ----
        {
            u64 acc[4][2] = {};
            gemm_g(sATs, g_Wc[l], lane, rg, kq, acc);
            store_part8(sPart, acc, lane, rg, kq);
            __syncthreads();
            float cbv = g_cb[l][cc];
#pragma unroll
            for (int q = 0; q < 2; q++) {
                int idx = q * 512 + tid;
                int r = rr + q * 4;
                float v = reduce8(sPart, idx) + sPn[r * 128 + cc] + s_rs[r] * cbv;
                v = fmaxf(v, 0.f);
                *(float2*)(sNTs + cc * 20 + 2 * r) = make_float2(v, v);
            }
            __syncthreads();
        }

        // ---- x += nh @ nw2 + nb2 ----
        {
            u64 acc[4][2] = {};
            gemm_g(sNTs, nw2 + l * 16384, lane, rg, kq, acc);
            store_part8(sPart, acc, lane, rg, kq);
            __syncthreads();
            float bv = nb2[l * 128 + cc];
#pragma unroll
            for (int q = 0; q < 2; q++) {
                int idx = q * 512 + tid;
                float v = sX[idx] + reduce8(sPart, idx) + bv;
                sX[idx] = v;
                if (l == L_ - 1) x[rb * 1024 + idx] = v;
            }
            __syncthreads();
        }
    }
}

// ---------------- launch ----------------
extern "C" void kernel_launch(void* const* d_in, const int* in_sizes, int n_in,
                              void* d_out, int out_size) {
    const float* nf  = (const float*)d_in[0];
    const float* adj = (const float*)d_in[1];
    const float* ew1 = (const float*)d_in[2];
    const float* eb1 = (const float*)d_in[3];
    const float* ew2 = (const float*)d_in[4];
    const float* eb2 = (const float*)d_in[5];
    const float* nw1 = (const float*)d_in[6];
    const float* nb1 = (const float*)d_in[7];
    const float* nw2 = (const float*)d_in[8];
    const float* nb2 = (const float*)d_in[9];
    float* x = (float*)d_out;

    const int SMEM = SMEM_FLOATS * 4;   // 81956 B
    cudaFuncSetAttribute(k_main, cudaFuncAttributeMaxDynamicSharedMemorySize, SMEM);
    k_main<<<NB, NT, SMEM>>>(x, nf, adj, ew1, eb1, ew2, eb2, nw1, nb1, nw2, nb2);
}